// round 8
// baseline (speedup 1.0000x reference)
#include <cuda_runtime.h>
#include <math.h>
#include <stdint.h>

__device__ float g_L [2u*4096u*1024u];
__device__ float g_G [2u*4096u*1024u];
__device__ float g_BC[2u*4096u*1024u];
__device__ float g_M [2u*4096u*1024u];
__device__ float g_COMP[2u*64u*1024u];
__device__ float g_W1[2048u*1024u];   // mix_w, tf32-RN-rounded
__device__ float g_W2[1024u*1024u];   // out_w, tf32-RN-rounded

__device__ __forceinline__ float f2tff(float x) {
    uint32_t u; asm("cvt.rn.tf32.f32 %0, %1;" : "=r"(u) : "f"(x));
    return __uint_as_float(u);
}
__device__ __forceinline__ void mma8(float* c, const uint32_t* a, const uint32_t* b) {
    asm volatile("mma.sync.aligned.m16n8k8.row.col.f32.tf32.tf32.f32 "
        "{%0,%1,%2,%3}, {%4,%5,%6,%7}, {%8,%9}, {%0,%1,%2,%3};"
        : "+f"(c[0]), "+f"(c[1]), "+f"(c[2]), "+f"(c[3])
        : "r"(a[0]), "r"(a[1]), "r"(a[2]), "r"(a[3]), "r"(b[0]), "r"(b[1]));
}
__device__ __forceinline__ uint32_t smem_u32(const void* p) {
    uint32_t a;
    asm("{ .reg .u64 t; cvta.to.shared.u64 t, %1; cvt.u32.u64 %0, t; }" : "=r"(a) : "l"(p));
    return a;
}
#define CP16(dst, src) asm volatile("cp.async.cg.shared.global [%0], [%1], 16;" :: "r"(dst), "l"(src))
#define CPCOMMIT()     asm volatile("cp.async.commit_group;" ::: "memory")
#define CPWAIT1()      asm volatile("cp.async.wait_group 1;" ::: "memory")

__device__ __forceinline__ float invden(int s) {
    int n1 = s >> 8, i1 = s & 255;
    float d = 0.f;
    if (n1 <= 14) d += 0.5f + (float)i1 * (1.0f / 511.0f);
    if (n1 >= 1)  d += 0.5f + (float)(i1 + 256) * (1.0f / 511.0f);
    return 1.0f / d;
}

// ============ 0) weight tf32-RN pre-rounding ============
__global__ void wround(const float* __restrict__ W, float* __restrict__ WR) {
    size_t i = ((size_t)blockIdx.x * blockDim.x + threadIdx.x) << 2;
    float4 v = *(const float4*)(W + i);
    v.x = f2tff(v.x); v.y = f2tff(v.y); v.z = f2tff(v.z); v.w = f2tff(v.w);
    *(float4*)(WR + i) = v;
}

// ============ 1) broadcast diffusion v2 (conflict-free planes) ============
__global__ void bc_kernel(const float* __restrict__ x, float* __restrict__ bc) {
    extern __shared__ float sm[];      // 2 buffers x 4 planes x 4096
    const int tid = threadIdx.x, b = blockIdx.y, d0 = blockIdx.x << 2;
    float* bufA = sm; float* bufB = sm + 16384;
    const float* src = x + (size_t)b * 4194304u + d0;
    for (int s = tid; s < 4096; s += 512) {
        float4 v = *(const float4*)(src + (size_t)s * 1024u);
        bufA[s] = v.x; bufA[4096 + s] = v.y; bufA[8192 + s] = v.z; bufA[12288 + s] = v.w;
    }
    __syncthreads();
    float acc[32];
#pragma unroll
    for (int e = 0; e < 32; ++e) acc[e] = 0.f;
    float* cur = bufA; float* nxt = bufB;
    for (int st = 1; st < 4096; st <<= 1) {
#pragma unroll
        for (int q = 0; q < 8; ++q) {
            int s = tid + (q << 9);
            int sm1 = (s - st) & 4095, sp1 = (s + st) & 4095;
#pragma unroll
            for (int j = 0; j < 4; ++j) {
                const float* cj = cur + (j << 12);
                float v = cj[s] + 0.5f * (cj[sm1] + cj[sp1]);
                nxt[(j << 12) + s] = v;
                acc[(q << 2) + j] += v;
            }
        }
        __syncthreads();
        float* t = cur; cur = nxt; nxt = t;
    }
    const float inv = 1.0f / 13.0f;
    float* dst = bc + (size_t)b * 4194304u + d0;
#pragma unroll
    for (int q = 0; q < 8; ++q) {
        int s = tid + (q << 9);
        *(float4*)(dst + (size_t)s * 1024u) =
            make_float4(acc[q*4]*inv, acc[q*4+1]*inv, acc[q*4+2]*inv, acc[q*4+3]*inv);
    }
}

// ============ 2) conv1d(k=4,s=4), first 64 tokens ============
__global__ void __launch_bounds__(256) conv_kernel(
        const float* __restrict__ x, const float* __restrict__ cw,
        const float* __restrict__ cb, float* __restrict__ comp) {
    __shared__ float As[32 * 129];
    __shared__ float Ws[32 * 20];
    const int tid = threadIdx.x, o0 = blockIdx.x << 4;
    const int mb = (tid & 31) << 2, og = (tid >> 5) << 1;
    float acc[4][2];
#pragma unroll
    for (int r = 0; r < 4; ++r) { acc[r][0] = 0.f; acc[r][1] = 0.f; }
    for (int k0 = 0; k0 < 4096; k0 += 32) {
        __syncthreads();
#pragma unroll
        for (int it = 0; it < 16; ++it) {
            int idx = tid + (it << 8);
            int m = idx & 127, kc = idx >> 7, k = k0 + kc;
            int bb = m >> 6, t = m & 63;
            As[kc * 129 + m] =
                x[(size_t)bb * 4194304u + (size_t)((t << 2) + (k & 3)) * 1024u + (k >> 2)];
        }
#pragma unroll
        for (int it = 0; it < 2; ++it) {
            int idx = tid + (it << 8);
            int oo = idx >> 5, kc = idx & 31;
            Ws[kc * 20 + oo] = cw[(size_t)(o0 + oo) * 4096u + k0 + kc];
        }
        __syncthreads();
#pragma unroll
        for (int kc = 0; kc < 32; ++kc) {
            float a0 = As[kc*129+mb], a1 = As[kc*129+mb+1];
            float a2 = As[kc*129+mb+2], a3 = As[kc*129+mb+3];
            float w0 = Ws[kc*20+og], w1 = Ws[kc*20+og+1];
            acc[0][0]+=a0*w0; acc[0][1]+=a0*w1; acc[1][0]+=a1*w0; acc[1][1]+=a1*w1;
            acc[2][0]+=a2*w0; acc[2][1]+=a2*w1; acc[3][0]+=a3*w0; acc[3][1]+=a3*w1;
        }
    }
#pragma unroll
    for (int r = 0; r < 4; ++r)
#pragma unroll
        for (int c = 0; c < 2; ++c) {
            int m = mb + r, o = o0 + og + c;
            comp[(size_t)m * 1024u + o] = acc[r][c] + cb[o];
        }
}

// ============ 3) sliding-window attention (TC, fused normalization) ============
__global__ void __launch_bounds__(256) win_attn(
        const float* __restrict__ x, float* __restrict__ L, int parity) {
    extern __shared__ float sm[];
    float* Qs = sm;              // 8448
    float* Ks = sm + 8448;       // 8448
    float* Ss = sm + 16896;      // 4352
    float* Al = sm + 21248;      // 64
    const int tid = threadIdx.x;
    const int lane = tid & 31, wid = tid >> 5;
    const int g = lane >> 2, tq = lane & 3;
    const int qt = blockIdx.x;
    const int n = (blockIdx.y << 1) + parity;
    const int b = blockIdx.z >> 3, h = blockIdx.z & 7;
    const int base = n << 8, q0 = base + (qt << 6);
    const float* xb = x + (size_t)b * 4194304u + (h << 7);

#pragma unroll
    for (int it = 0; it < 8; ++it) {
        int i = tid + (it << 8);
        int r = i >> 5, c4 = (i & 31) << 2;
        float4 v = *(const float4*)(xb + (size_t)(q0 + r) * 1024u + c4);
        float* q = &Qs[r * 132 + c4];
        q[0] = f2tff(v.x); q[1] = f2tff(v.y); q[2] = f2tff(v.z); q[3] = f2tff(v.w);
    }

    const int wm = wid >> 1, wn = wid & 1;
    const int m0 = wm << 4;
    const int sn0 = wn << 5;
    const int on0 = wn << 6;
    const int srow = tid >> 2, seg = tid & 3;
    const float scale = 0.08838834764831845f;

    float oacc[8][4];
#pragma unroll
    for (int nt = 0; nt < 8; ++nt)
#pragma unroll
        for (int e = 0; e < 4; ++e) oacc[nt][e] = 0.f;
    float m_i = -1e30f, l_i = 0.f;

    for (int kt = 0; kt < 8; ++kt) {
        __syncthreads();
        const int ktok = base + (kt << 6);
#pragma unroll
        for (int it = 0; it < 8; ++it) {
            int i = tid + (it << 8);
            int r = i >> 5, c4 = (i & 31) << 2;
            float4 v = *(const float4*)(xb + (size_t)(ktok + r) * 1024u + c4);
            float* k = &Ks[r * 132 + c4];
            k[0] = f2tff(v.x); k[1] = f2tff(v.y); k[2] = f2tff(v.z); k[3] = f2tff(v.w);
        }
        __syncthreads();

        float sacc[4][4];
#pragma unroll
        for (int nt = 0; nt < 4; ++nt)
#pragma unroll
            for (int e = 0; e < 4; ++e) sacc[nt][e] = 0.f;
#pragma unroll
        for (int kd = 0; kd < 128; kd += 8) {
            uint32_t a[4];
            a[0] = __float_as_uint(Qs[(m0 + g) * 132 + kd + tq]);
            a[1] = __float_as_uint(Qs[(m0 + g + 8) * 132 + kd + tq]);
            a[2] = __float_as_uint(Qs[(m0 + g) * 132 + kd + tq + 4]);
            a[3] = __float_as_uint(Qs[(m0 + g + 8) * 132 + kd + tq + 4]);
#pragma unroll
            for (int nt = 0; nt < 4; ++nt) {
                int tcol = sn0 + (nt << 3) + g;
                uint32_t bb[2];
                bb[0] = __float_as_uint(Ks[tcol * 132 + kd + tq]);
                bb[1] = __float_as_uint(Ks[tcol * 132 + kd + tq + 4]);
                mma8(sacc[nt], a, bb);
            }
        }
#pragma unroll
        for (int nt = 0; nt < 4; ++nt) {
            int nc = sn0 + (nt << 3) + (tq << 1);
            *(float2*)&Ss[(m0 + g) * 68 + nc] =
                make_float2(sacc[nt][0] * scale, sacc[nt][1] * scale);
            *(float2*)&Ss[(m0 + g + 8) * 68 + nc] =
                make_float2(sacc[nt][2] * scale, sacc[nt][3] * scale);
        }
        __syncthreads();

        {
            float* sr = &Ss[srow * 68 + (seg << 4)];
            float mt = -1e30f;
#pragma unroll
            for (int jj = 0; jj < 16; ++jj) mt = fmaxf(mt, sr[jj]);
            mt = fmaxf(mt, __shfl_xor_sync(0xffffffffu, mt, 1));
            mt = fmaxf(mt, __shfl_xor_sync(0xffffffffu, mt, 2));
            float m_new = fmaxf(m_i, mt);
            float alpha = __expf(m_i - m_new);
            float ls = 0.f;
#pragma unroll
            for (int jj = 0; jj < 16; ++jj) {
                float p = __expf(sr[jj] - m_new);
                ls += p;
                sr[jj] = f2tff(p);
            }
            ls += __shfl_xor_sync(0xffffffffu, ls, 1);
            ls += __shfl_xor_sync(0xffffffffu, ls, 2);
            l_i = l_i * alpha + ls;
            m_i = m_new;
            if (seg == 0) Al[srow] = alpha;
        }
        __syncthreads();

        float aLo = Al[m0 + g], aHi = Al[m0 + g + 8];
#pragma unroll
        for (int nt = 0; nt < 8; ++nt) {
            oacc[nt][0] *= aLo; oacc[nt][1] *= aLo;
            oacc[nt][2] *= aHi; oacc[nt][3] *= aHi;
        }
#pragma unroll
        for (int kd = 0; kd < 64; kd += 8) {
            uint32_t a[4];
            a[0] = __float_as_uint(Ss[(m0 + g) * 68 + kd + tq]);
            a[1] = __float_as_uint(Ss[(m0 + g + 8) * 68 + kd + tq]);
            a[2] = __float_as_uint(Ss[(m0 + g) * 68 + kd + tq + 4]);
            a[3] = __float_as_uint(Ss[(m0 + g + 8) * 68 + kd + tq + 4]);
#pragma unroll
            for (int nt = 0; nt < 8; ++nt) {
                int dcol = on0 + (nt << 3) + g;
                uint32_t bb[2];
                bb[0] = __float_as_uint(Ks[(kd + tq) * 132 + dcol]);
                bb[1] = __float_as_uint(Ks[(kd + tq + 4) * 132 + dcol]);
                mma8(oacc[nt], a, bb);
            }
        }
    }
    __syncthreads();
    if (seg == 0) Al[srow] = 1.0f / l_i;
    __syncthreads();

    const int iwLo = (qt << 6) + m0 + g;
    const int iwHi = iwLo + 8;
    const int sLo = base + iwLo, sHi = base + iwHi;
    const float triLo = 0.5f + (float)iwLo * (1.0f / 511.0f);
    const float triHi = 0.5f + (float)iwHi * (1.0f / 511.0f);
    float* dLo = L + ((size_t)b * 4096u + sLo) * 1024u + (h << 7);
    float* dHi = dLo + (size_t)8 * 1024u;
    if (parity == 0) {
        const bool snLo = (sLo < 256) || (sLo >= 3840);
        const bool snHi = (sHi < 256) || (sHi >= 3840);
        const float twLo = (snLo ? 1.0f : triLo) * Al[m0 + g];
        const float twHi = (snHi ? 1.0f : triHi) * Al[m0 + g + 8];
#pragma unroll
        for (int nt = 0; nt < 8; ++nt) {
            int dc = on0 + (nt << 3) + (tq << 1);
            *(float2*)(dLo + dc) = make_float2(oacc[nt][0] * twLo, oacc[nt][1] * twLo);
            *(float2*)(dHi + dc) = make_float2(oacc[nt][2] * twHi, oacc[nt][3] * twHi);
        }
    } else {
        const float twLo = triLo * Al[m0 + g];
        const float twHi = triHi * Al[m0 + g + 8];
        const float ivLo = invden(sLo), ivHi = invden(sHi);
#pragma unroll
        for (int nt = 0; nt < 8; ++nt) {
            int dc = on0 + (nt << 3) + (tq << 1);
            float2 o = *(float2*)(dLo + dc);
            o.x = (o.x + oacc[nt][0] * twLo) * ivLo;
            o.y = (o.y + oacc[nt][1] * twLo) * ivLo;
            *(float2*)(dLo + dc) = o;
            float2 p = *(float2*)(dHi + dc);
            p.x = (p.x + oacc[nt][2] * twHi) * ivHi;
            p.y = (p.y + oacc[nt][3] * twHi) * ivHi;
            *(float2*)(dHi + dc) = p;
        }
    }
}

// ============ 4) compressed-global attention (TC) ============
__global__ void __launch_bounds__(256) gattn(
        const float* __restrict__ x, const float* __restrict__ gmem,
        const float* __restrict__ comp, float* __restrict__ G) {
    extern __shared__ float sm[];
    float* KVs = sm;
    float* Qs  = sm + 16896;
    float* Ps  = sm + 21120;
    const int tid = threadIdx.x;
    const int lane = tid & 31, wid = tid >> 5;
    const int g = lane >> 2, tq = lane & 3;
    const int s0 = blockIdx.x << 5, h = blockIdx.y, b = blockIdx.z;

#pragma unroll
    for (int it = 0; it < 16; ++it) {
        int i = tid + (it << 8);
        int r = i >> 5, c4 = (i & 31) << 2;
        float4 v;
        if (r < 64) v = *(const float4*)(comp + (size_t)((b << 6) + r) * 1024u + (h << 7) + c4);
        else        v = *(const float4*)(gmem + (size_t)((h << 6) + (r - 64)) * 128u + c4);
        float* kv = &KVs[r * 132 + c4];
        kv[0] = f2tff(v.x); kv[1] = f2tff(v.y); kv[2] = f2tff(v.z); kv[3] = f2tff(v.w);
    }
#pragma unroll
    for (int it = 0; it < 4; ++it) {
        int i = tid + (it << 8);
        int r = i >> 5, c4 = (i & 31) << 2;
        float4 v = *(const float4*)(x + (size_t)b * 4194304u + (size_t)(s0 + r) * 1024u + (h << 7) + c4);
        float* q = &Qs[r * 132 + c4];
        q[0] = f2tff(v.x); q[1] = f2tff(v.y); q[2] = f2tff(v.z); q[3] = f2tff(v.w);
    }
    __syncthreads();

    const int wm = wid & 1, wn = wid >> 1;
    const int m0 = wm << 4;
    const int tn0 = wn << 5;
    const float scale = 0.08838834764831845f;

    {
        float sacc[4][4];
#pragma unroll
        for (int nt = 0; nt < 4; ++nt)
#pragma unroll
            for (int e = 0; e < 4; ++e) sacc[nt][e] = 0.f;
#pragma unroll
        for (int kd = 0; kd < 128; kd += 8) {
            uint32_t a[4];
            a[0] = __float_as_uint(Qs[(m0 + g) * 132 + kd + tq]);
            a[1] = __float_as_uint(Qs[(m0 + g + 8) * 132 + kd + tq]);
            a[2] = __float_as_uint(Qs[(m0 + g) * 132 + kd + tq + 4]);
            a[3] = __float_as_uint(Qs[(m0 + g + 8) * 132 + kd + tq + 4]);
#pragma unroll
            for (int nt = 0; nt < 4; ++nt) {
                int tcol = tn0 + (nt << 3) + g;
                uint32_t bb[2];
                bb[0] = __float_as_uint(KVs[tcol * 132 + kd + tq]);
                bb[1] = __float_as_uint(KVs[tcol * 132 + kd + tq + 4]);
                mma8(sacc[nt], a, bb);
            }
        }
#pragma unroll
        for (int nt = 0; nt < 4; ++nt) {
            int nc = tn0 + (nt << 3) + (tq << 1);
            *(float2*)&Ps[(m0 + g) * 132 + nc] =
                make_float2(sacc[nt][0] * scale, sacc[nt][1] * scale);
            *(float2*)&Ps[(m0 + g + 8) * 132 + nc] =
                make_float2(sacc[nt][2] * scale, sacc[nt][3] * scale);
        }
    }
    __syncthreads();

    {
        int row = tid >> 3, seg8 = tid & 7;
        float* pr = &Ps[row * 132 + (seg8 << 4)];
        float mt = -1e30f;
        float pv[16];
#pragma unroll
        for (int jj = 0; jj < 16; ++jj) mt = fmaxf(mt, pr[jj]);
        mt = fmaxf(mt, __shfl_xor_sync(0xffffffffu, mt, 1));
        mt = fmaxf(mt, __shfl_xor_sync(0xffffffffu, mt, 2));
        mt = fmaxf(mt, __shfl_xor_sync(0xffffffffu, mt, 4));
        float ssum = 0.f;
#pragma unroll
        for (int jj = 0; jj < 16; ++jj) { pv[jj] = __expf(pr[jj] - mt); ssum += pv[jj]; }
        ssum += __shfl_xor_sync(0xffffffffu, ssum, 1);
        ssum += __shfl_xor_sync(0xffffffffu, ssum, 2);
        ssum += __shfl_xor_sync(0xffffffffu, ssum, 4);
        float invs = 1.0f / ssum;
#pragma unroll
        for (int jj = 0; jj < 16; ++jj) pr[jj] = f2tff(pv[jj] * invs);
    }
    __syncthreads();

    {
        float oacc[4][4];
#pragma unroll
        for (int nt = 0; nt < 4; ++nt)
#pragma unroll
            for (int e = 0; e < 4; ++e) oacc[nt][e] = 0.f;
#pragma unroll
        for (int kd = 0; kd < 128; kd += 8) {
            uint32_t a[4];
            a[0] = __float_as_uint(Ps[(m0 + g) * 132 + kd + tq]);
            a[1] = __float_as_uint(Ps[(m0 + g + 8) * 132 + kd + tq]);
            a[2] = __float_as_uint(Ps[(m0 + g) * 132 + kd + tq + 4]);
            a[3] = __float_as_uint(Ps[(m0 + g + 8) * 132 + kd + tq + 4]);
#pragma unroll
            for (int nt = 0; nt < 4; ++nt) {
                int dcol = tn0 + (nt << 3) + g;
                uint32_t bb[2];
                bb[0] = __float_as_uint(KVs[(kd + tq) * 132 + dcol]);
                bb[1] = __float_as_uint(KVs[(kd + tq + 4) * 132 + dcol]);
                mma8(oacc[nt], a, bb);
            }
        }
        float* gLo = G + ((size_t)b * 4096u + s0 + m0 + g) * 1024u + (h << 7);
        float* gHi = gLo + (size_t)8 * 1024u;
#pragma unroll
        for (int nt = 0; nt < 4; ++nt) {
            int nc = tn0 + (nt << 3) + (tq << 1);
            *(float2*)(gLo + nc) = make_float2(oacc[nt][0], oacc[nt][1]);
            *(float2*)(gHi + nc) = make_float2(oacc[nt][2], oacc[nt][3]);
        }
    }
}

// ============ 5+6) cp.async-pipelined tf32 GEMM (mma.sync) ============
__global__ void __launch_bounds__(256) gemm_tc(
        int mode, const float* __restrict__ A0, const float* __restrict__ A1,
        const float* __restrict__ BCp, const float* __restrict__ W,
        const float* __restrict__ bias, float* __restrict__ C, int K) {
    extern __shared__ float gsm[];
    const int tid = threadIdx.x;
    const int m0 = blockIdx.x << 7, n0 = blockIdx.y << 7;
    const int wid = tid >> 5, lane = tid & 31;
    const int quad = lane >> 2, tq = lane & 3;
    const int wm = wid >> 2, wn = wid & 3;
    const int am = tid >> 1, ak = (tid & 1) << 4;
    const int bk = tid >> 3, bn = (tid & 7) << 4;
    const uint32_t sbase = smem_u32(gsm);

    auto issue = [&](int kt, int slot) {
        uint32_t aoff = sbase + (uint32_t)(slot * 8960 + am * 36 + ak) * 4u;
        const float* asrc = (mode == 1 && kt >= 1024)
            ? (A1 + (size_t)(m0 + am) * 1024u + (kt - 1024) + ak)
            : (A0 + (size_t)(m0 + am) * 1024u + kt + ak);
        CP16(aoff, asrc); CP16(aoff + 16, asrc + 4);
        CP16(aoff + 32, asrc + 8); CP16(aoff + 48, asrc + 12);
        uint32_t boff = sbase + (uint32_t)(slot * 8960 + 4608 + bk * 136 + bn) * 4u;
        const float* bsrc = W + (size_t)(kt + bk) * 1024u + n0 + bn;
        CP16(boff, bsrc); CP16(boff + 16, bsrc + 4);
        CP16(boff + 32, bsrc + 8); CP16(boff + 48, bsrc + 12);
        CPCOMMIT();
    };

    float acc[4][4][4];
#pragma unroll
    for (int i = 0; i < 4; ++i)
#pragma unroll
        for (int j = 0; j < 4; ++j)
#pragma unroll
            for (int e = 0; e < 4; ++e) acc[i][j][e] = 0.f;

    issue(0, 0);
    issue(32, 1);

    for (int kt = 0; kt < K; kt += 32) {
        CPWAIT1();
        __syncthreads();
        int nk = kt + 64;
        if (nk < K) issue(nk, ((kt >> 5) + 2) % 3);
        else        CPCOMMIT();

        const float* Asb = gsm + ((kt >> 5) % 3) * 8960;
        const float* Bsb = Asb + 4608;
#pragma unroll
        for (int ks = 0; ks < 4; ++ks) {
            const int k0 = ks << 3;
            uint32_t af[4][4], bf[4][2];
#pragma unroll
            for (int i = 0; i < 4; ++i) {
                int r = (wm << 6) + (i << 4) + quad;
                af[i][0] = __float_as_uint(Asb[r * 36 + k0 + tq]);
                af[i][1] = __float_as_uint(Asb[(r + 8) * 36 + k0 + tq]);
                af[i][2] = __float_as_uint(Asb[r * 36 + k0 + tq + 4]);
                af[i][3] = __float_as_uint(Asb[(r + 8) * 36 + k0 + tq + 4]);
            }
#pragma unroll
            for (int j = 0; j < 4; ++j) {
                int cidx = (wn << 5) + (j << 3) + quad;
                bf[j][0] = __float_as_uint(Bsb[(k0 + tq) * 136 + cidx]);
                bf[j][1] = __float_as_uint(Bsb[(k0 + tq + 4) * 136 + cidx]);
            }
#pragma unroll
            for (int i = 0; i < 4; ++i)
#pragma unroll
                for (int j = 0; j < 4; ++j) mma8(acc[i][j], af[i], bf[j]);
        }
    }

#pragma unroll
    for (int i = 0; i < 4; ++i)
#pragma unroll
        for (int j = 0; j < 4; ++j) {
            int mr = m0 + (wm << 6) + (i << 4) + quad;
            int nc = n0 + (wn << 5) + (j << 3) + (tq << 1);
#pragma unroll
            for (int hf = 0; hf < 2; ++hf) {
                int m = mr + (hf << 3);
                size_t bix = (size_t)m * 1024u + nc;
#pragma unroll
                for (int e = 0; e < 2; ++e) {
                    float z = acc[i][j][(hf << 1) + e] + bias[nc + e];
                    if (mode == 1) {
                        float gg = 1.0f / (1.0f + __expf(-z));
                        C[bix + e] = gg * A0[bix + e] + (1.0f - gg) * A1[bix + e] + BCp[bix + e];
                    } else {
                        C[bix + e] = z;
                    }
                }
            }
        }
}

// =====================================================================
extern "C" void kernel_launch(void* const* d_in, const int* in_sizes, int n_in,
                              void* d_out, int out_size) {
    const float* x    = (const float*)d_in[0];
    const float* gmem = (const float*)d_in[1];
    const float* cw   = (const float*)d_in[2];
    const float* cb   = (const float*)d_in[3];
    const float* mw   = (const float*)d_in[4];
    const float* mb   = (const float*)d_in[5];
    const float* ow   = (const float*)d_in[6];
    const float* ob   = (const float*)d_in[7];
    float* out = (float*)d_out;

    float *pL, *pG, *pBC, *pM, *pCOMP, *pW1, *pW2;
    cudaGetSymbolAddress((void**)&pL,    g_L);
    cudaGetSymbolAddress((void**)&pG,    g_G);
    cudaGetSymbolAddress((void**)&pBC,   g_BC);
    cudaGetSymbolAddress((void**)&pM,    g_M);
    cudaGetSymbolAddress((void**)&pCOMP, g_COMP);
    cudaGetSymbolAddress((void**)&pW1,   g_W1);
    cudaGetSymbolAddress((void**)&pW2,   g_W2);

    static cudaStream_t s1 = nullptr, s2 = nullptr, s3 = nullptr;
    static cudaEvent_t evR = nullptr, ev1 = nullptr, ev2 = nullptr, ev3 = nullptr;
    if (s1 == nullptr) {
        cudaStreamCreateWithFlags(&s1, cudaStreamNonBlocking);
        cudaStreamCreateWithFlags(&s2, cudaStreamNonBlocking);
        cudaStreamCreateWithFlags(&s3, cudaStreamNonBlocking);
        cudaEventCreateWithFlags(&evR, cudaEventDisableTiming);
        cudaEventCreateWithFlags(&ev1, cudaEventDisableTiming);
        cudaEventCreateWithFlags(&ev2, cudaEventDisableTiming);
        cudaEventCreateWithFlags(&ev3, cudaEventDisableTiming);
    }

    const int BC_SMEM = 2 * 16384 * 4;     // 128 KB
    const int WA_SMEM = 21312 * 4;
    const int GA_SMEM = 25344 * 4;
    const int GE_SMEM = 3 * 8960 * 4;      // 107520 B
    cudaFuncSetAttribute(bc_kernel, cudaFuncAttributeMaxDynamicSharedMemorySize, BC_SMEM);
    cudaFuncSetAttribute(win_attn,  cudaFuncAttributeMaxDynamicSharedMemorySize, WA_SMEM);
    cudaFuncSetAttribute(gattn,     cudaFuncAttributeMaxDynamicSharedMemorySize, GA_SMEM);
    cudaFuncSetAttribute(gemm_tc,   cudaFuncAttributeMaxDynamicSharedMemorySize, GE_SMEM);

    cudaEventRecord(evR, 0);
    cudaStreamWaitEvent(s1, evR, 0);
    cudaStreamWaitEvent(s2, evR, 0);
    cudaStreamWaitEvent(s3, evR, 0);

    wround     <<<2048, 256, 0, s1>>>(mw, pW1);   // 2M elems / (256*4)
    wround     <<<1024, 256, 0, s1>>>(ow, pW2);
    bc_kernel  <<<dim3(256, 2), 512, BC_SMEM, s1>>>(x, pBC);
    conv_kernel<<<64, 256, 0, s2>>>(x, cw, cb, pCOMP);
    gattn      <<<dim3(128, 8, 2), 256, GA_SMEM, s2>>>(x, gmem, pCOMP, pG);
    win_attn   <<<dim3(8, 8, 16), 256, WA_SMEM, s3>>>(x, pL, 0);
    win_attn   <<<dim3(8, 7, 16), 256, WA_SMEM, s3>>>(x, pL, 1);

    cudaEventRecord(ev1, s1);
    cudaEventRecord(ev2, s2);
    cudaEventRecord(ev3, s3);
    cudaStreamWaitEvent(0, ev1, 0);
    cudaStreamWaitEvent(0, ev2, 0);
    cudaStreamWaitEvent(0, ev3, 0);

    gemm_tc<<<dim3(64, 8), 256, GE_SMEM>>>(1, pL, pG, pBC, pW1, mb, pM, 2048);
    gemm_tc<<<dim3(64, 8), 256, GE_SMEM>>>(0, pM, pM, pBC, pW2, ob, out, 1024);
}

// round 9
// speedup vs baseline: 2.2143x; 2.2143x over previous
#include <cuda_runtime.h>
#include <math.h>
#include <stdint.h>

__device__ float g_L [2u*4096u*1024u];
__device__ float g_G [2u*4096u*1024u];
__device__ float g_BC[2u*4096u*1024u];
__device__ float g_M [2u*4096u*1024u];
__device__ float g_COMP[2u*64u*1024u];
__device__ float g_W1[2048u*1024u];   // mix_w, tf32-RN
__device__ float g_W2[1024u*1024u];   // out_w, tf32-RN
__device__ float g_XC[128u*4096u];    // gathered conv input
__device__ float g_CP[4u*128u*1024u]; // conv split-K partials

__device__ __forceinline__ float f2tff(float x) {
    uint32_t u; asm("cvt.rn.tf32.f32 %0, %1;" : "=r"(u) : "f"(x));
    return __uint_as_float(u);
}
__device__ __forceinline__ void mma8(float* c, const uint32_t* a, const uint32_t* b) {
    asm volatile("mma.sync.aligned.m16n8k8.row.col.f32.tf32.tf32.f32 "
        "{%0,%1,%2,%3}, {%4,%5,%6,%7}, {%8,%9}, {%0,%1,%2,%3};"
        : "+f"(c[0]), "+f"(c[1]), "+f"(c[2]), "+f"(c[3])
        : "r"(a[0]), "r"(a[1]), "r"(a[2]), "r"(a[3]), "r"(b[0]), "r"(b[1]));
}
__device__ __forceinline__ uint32_t smem_u32(const void* p) {
    uint32_t a;
    asm("{ .reg .u64 t; cvta.to.shared.u64 t, %1; cvt.u32.u64 %0, t; }" : "=r"(a) : "l"(p));
    return a;
}
#define CP16(dst, src) asm volatile("cp.async.cg.shared.global [%0], [%1], 16;" :: "r"(dst), "l"(src))
#define CPCOMMIT()     asm volatile("cp.async.commit_group;" ::: "memory")
#define CPWAIT1()      asm volatile("cp.async.wait_group 1;" ::: "memory")

__device__ __forceinline__ float invden(int s) {
    int n1 = s >> 8, i1 = s & 255;
    float d = 0.f;
    if (n1 <= 14) d += 0.5f + (float)i1 * (1.0f / 511.0f);
    if (n1 >= 1)  d += 0.5f + (float)(i1 + 256) * (1.0f / 511.0f);
    return 1.0f / d;
}

// ============ 0) weight tf32-RN pre-rounding ============
__global__ void wround(const float* __restrict__ W, float* __restrict__ WR) {
    size_t i = ((size_t)blockIdx.x * blockDim.x + threadIdx.x) << 2;
    float4 v = *(const float4*)(W + i);
    v.x = f2tff(v.x); v.y = f2tff(v.y); v.z = f2tff(v.z); v.w = f2tff(v.w);
    *(float4*)(WR + i) = v;
}

// ============ 1) broadcast diffusion (conflict-free planes) ============
__global__ void bc_kernel(const float* __restrict__ x, float* __restrict__ bc) {
    extern __shared__ float sm[];
    const int tid = threadIdx.x, b = blockIdx.y, d0 = blockIdx.x << 2;
    float* bufA = sm; float* bufB = sm + 16384;
    const float* src = x + (size_t)b * 4194304u + d0;
    for (int s = tid; s < 4096; s += 512) {
        float4 v = *(const float4*)(src + (size_t)s * 1024u);
        bufA[s] = v.x; bufA[4096 + s] = v.y; bufA[8192 + s] = v.z; bufA[12288 + s] = v.w;
    }
    __syncthreads();
    float acc[32];
#pragma unroll
    for (int e = 0; e < 32; ++e) acc[e] = 0.f;
    float* cur = bufA; float* nxt = bufB;
    for (int st = 1; st < 4096; st <<= 1) {
#pragma unroll
        for (int q = 0; q < 8; ++q) {
            int s = tid + (q << 9);
            int sm1 = (s - st) & 4095, sp1 = (s + st) & 4095;
#pragma unroll
            for (int j = 0; j < 4; ++j) {
                const float* cj = cur + (j << 12);
                float v = cj[s] + 0.5f * (cj[sm1] + cj[sp1]);
                nxt[(j << 12) + s] = v;
                acc[(q << 2) + j] += v;
            }
        }
        __syncthreads();
        float* t = cur; cur = nxt; nxt = t;
    }
    const float inv = 1.0f / 13.0f;
    float* dst = bc + (size_t)b * 4194304u + d0;
#pragma unroll
    for (int q = 0; q < 8; ++q) {
        int s = tid + (q << 9);
        *(float4*)(dst + (size_t)s * 1024u) =
            make_float4(acc[q*4]*inv, acc[q*4+1]*inv, acc[q*4+2]*inv, acc[q*4+3]*inv);
    }
}

// ============ 2a) conv input gather: Xc[b*64+t][d*4+j] = x[b][4t+j][d] ============
__global__ void xc_kernel(const float* __restrict__ x, float* __restrict__ Xc) {
    const int s = blockIdx.x;           // 0..255
    const int b = blockIdx.y;           // 0..1
    const int t = s >> 2, j = s & 3;
    const int m = (b << 6) + t;
    const float* src = x + (size_t)b * 4194304u + (size_t)s * 1024u;
    float* dst = Xc + (size_t)m * 4096u + j;
#pragma unroll
    for (int k = 0; k < 4; ++k) {
        int d = threadIdx.x + (k << 8);
        dst[d << 2] = src[d];
    }
}

// ============ 2b) conv GEMM: CP[kq] = Xc[:, kq*1024:+1024] @ cwf^T ============
// M=128, N-tile 128, K-split 1024 per CTA. Both operands K-major.
__global__ void __launch_bounds__(256) conv_gemm(
        const float* __restrict__ Xc, const float* __restrict__ cwf,
        float* __restrict__ CP) {
    extern __shared__ float gsm[];
    const int tid = threadIdx.x;
    const int n0 = blockIdx.x << 7;
    const int kq = blockIdx.y;
    const int kbase = kq << 10;
    const int wid = tid >> 5, lane = tid & 31;
    const int quad = lane >> 2, tq = lane & 3;
    const int wm = wid >> 2, wn = wid & 3;
    const int am = tid >> 1, ak = (tid & 1) << 4;
    const uint32_t sbase = smem_u32(gsm);

    auto issue = [&](int kt, int slot) {
        uint32_t aoff = sbase + (uint32_t)(slot * 9216 + am * 36 + ak) * 4u;
        const float* asrc = Xc + (size_t)am * 4096u + kbase + kt + ak;
        CP16(aoff, asrc); CP16(aoff + 16, asrc + 4);
        CP16(aoff + 32, asrc + 8); CP16(aoff + 48, asrc + 12);
        uint32_t boff = aoff + 4608u * 4u;
        const float* bsrc = cwf + (size_t)(n0 + am) * 4096u + kbase + kt + ak;
        CP16(boff, bsrc); CP16(boff + 16, bsrc + 4);
        CP16(boff + 32, bsrc + 8); CP16(boff + 48, bsrc + 12);
        CPCOMMIT();
    };

    float acc[4][4][4];
#pragma unroll
    for (int i = 0; i < 4; ++i)
#pragma unroll
        for (int j = 0; j < 4; ++j)
#pragma unroll
            for (int e = 0; e < 4; ++e) acc[i][j][e] = 0.f;

    issue(0, 0);
    issue(32, 1);

    for (int kt = 0; kt < 1024; kt += 32) {
        CPWAIT1();
        __syncthreads();
        int nk = kt + 64;
        if (nk < 1024) issue(nk, ((kt >> 5) + 2) % 3);
        else           CPCOMMIT();

        const float* Asb = gsm + ((kt >> 5) % 3) * 9216;
        const float* Bsb = Asb + 4608;
#pragma unroll
        for (int ks = 0; ks < 4; ++ks) {
            const int k0 = ks << 3;
            uint32_t af[4][4], bf[4][2];
#pragma unroll
            for (int i = 0; i < 4; ++i) {
                int r = (wm << 6) + (i << 4) + quad;
                af[i][0] = __float_as_uint(Asb[r * 36 + k0 + tq]);
                af[i][1] = __float_as_uint(Asb[(r + 8) * 36 + k0 + tq]);
                af[i][2] = __float_as_uint(Asb[r * 36 + k0 + tq + 4]);
                af[i][3] = __float_as_uint(Asb[(r + 8) * 36 + k0 + tq + 4]);
            }
#pragma unroll
            for (int j = 0; j < 4; ++j) {
                int cidx = (wn << 5) + (j << 3) + quad;   // B row (n), K-major
                bf[j][0] = __float_as_uint(Bsb[cidx * 36 + k0 + tq]);
                bf[j][1] = __float_as_uint(Bsb[cidx * 36 + k0 + tq + 4]);
            }
#pragma unroll
            for (int i = 0; i < 4; ++i)
#pragma unroll
                for (int j = 0; j < 4; ++j) mma8(acc[i][j], af[i], bf[j]);
        }
    }
    float* cp = CP + (size_t)kq * 131072u;
#pragma unroll
    for (int i = 0; i < 4; ++i)
#pragma unroll
        for (int j = 0; j < 4; ++j) {
            int mr = (wm << 6) + (i << 4) + quad;
            int nc = n0 + (wn << 5) + (j << 3) + (tq << 1);
#pragma unroll
            for (int hf = 0; hf < 2; ++hf) {
                int m = mr + (hf << 3);
                *(float2*)(cp + (size_t)m * 1024u + nc) =
                    make_float2(acc[i][j][(hf << 1)], acc[i][j][(hf << 1) + 1]);
            }
        }
}

// ============ 2c) conv reduce: comp = sum_kq CP[kq] + cb ============
__global__ void conv_reduce(const float* __restrict__ CP, const float* __restrict__ cb,
                            float* __restrict__ comp) {
    int i = (blockIdx.x << 8) + threadIdx.x;   // float4 index, 32768 total
    int o4 = (i & 255) << 2;
    float4 a = *(const float4*)(CP + ((size_t)i << 2));
    float4 b = *(const float4*)(CP + 131072u + ((size_t)i << 2));
    float4 c = *(const float4*)(CP + 262144u + ((size_t)i << 2));
    float4 d = *(const float4*)(CP + 393216u + ((size_t)i << 2));
    float4 e = *(const float4*)(cb + o4);
    *(float4*)(comp + ((size_t)i << 2)) = make_float4(
        a.x + b.x + c.x + d.x + e.x, a.y + b.y + c.y + d.y + e.y,
        a.z + b.z + c.z + d.z + e.z, a.w + b.w + c.w + d.w + e.w);
}

// ============ 3) sliding-window attention (TC, fused normalization) ============
__global__ void __launch_bounds__(256) win_attn(
        const float* __restrict__ x, float* __restrict__ L, int parity) {
    extern __shared__ float sm[];
    float* Qs = sm;
    float* Ks = sm + 8448;
    float* Ss = sm + 16896;
    float* Al = sm + 21248;
    const int tid = threadIdx.x;
    const int lane = tid & 31, wid = tid >> 5;
    const int g = lane >> 2, tq = lane & 3;
    const int qt = blockIdx.x;
    const int n = (blockIdx.y << 1) + parity;
    const int b = blockIdx.z >> 3, h = blockIdx.z & 7;
    const int base = n << 8, q0 = base + (qt << 6);
    const float* xb = x + (size_t)b * 4194304u + (h << 7);

#pragma unroll
    for (int it = 0; it < 8; ++it) {
        int i = tid + (it << 8);
        int r = i >> 5, c4 = (i & 31) << 2;
        float4 v = *(const float4*)(xb + (size_t)(q0 + r) * 1024u + c4);
        float* q = &Qs[r * 132 + c4];
        q[0] = f2tff(v.x); q[1] = f2tff(v.y); q[2] = f2tff(v.z); q[3] = f2tff(v.w);
    }

    const int wm = wid >> 1, wn = wid & 1;
    const int m0 = wm << 4;
    const int sn0 = wn << 5;
    const int on0 = wn << 6;
    const int srow = tid >> 2, seg = tid & 3;
    const float scale = 0.08838834764831845f;

    float oacc[8][4];
#pragma unroll
    for (int nt = 0; nt < 8; ++nt)
#pragma unroll
        for (int e = 0; e < 4; ++e) oacc[nt][e] = 0.f;
    float m_i = -1e30f, l_i = 0.f;

    for (int kt = 0; kt < 8; ++kt) {
        __syncthreads();
        const int ktok = base + (kt << 6);
#pragma unroll
        for (int it = 0; it < 8; ++it) {
            int i = tid + (it << 8);
            int r = i >> 5, c4 = (i & 31) << 2;
            float4 v = *(const float4*)(xb + (size_t)(ktok + r) * 1024u + c4);
            float* k = &Ks[r * 132 + c4];
            k[0] = f2tff(v.x); k[1] = f2tff(v.y); k[2] = f2tff(v.z); k[3] = f2tff(v.w);
        }
        __syncthreads();

        float sacc[4][4];
#pragma unroll
        for (int nt = 0; nt < 4; ++nt)
#pragma unroll
            for (int e = 0; e < 4; ++e) sacc[nt][e] = 0.f;
#pragma unroll
        for (int kd = 0; kd < 128; kd += 8) {
            uint32_t a[4];
            a[0] = __float_as_uint(Qs[(m0 + g) * 132 + kd + tq]);
            a[1] = __float_as_uint(Qs[(m0 + g + 8) * 132 + kd + tq]);
            a[2] = __float_as_uint(Qs[(m0 + g) * 132 + kd + tq + 4]);
            a[3] = __float_as_uint(Qs[(m0 + g + 8) * 132 + kd + tq + 4]);
#pragma unroll
            for (int nt = 0; nt < 4; ++nt) {
                int tcol = sn0 + (nt << 3) + g;
                uint32_t bb[2];
                bb[0] = __float_as_uint(Ks[tcol * 132 + kd + tq]);
                bb[1] = __float_as_uint(Ks[tcol * 132 + kd + tq + 4]);
                mma8(sacc[nt], a, bb);
            }
        }
#pragma unroll
        for (int nt = 0; nt < 4; ++nt) {
            int nc = sn0 + (nt << 3) + (tq << 1);
            *(float2*)&Ss[(m0 + g) * 68 + nc] =
                make_float2(sacc[nt][0] * scale, sacc[nt][1] * scale);
            *(float2*)&Ss[(m0 + g + 8) * 68 + nc] =
                make_float2(sacc[nt][2] * scale, sacc[nt][3] * scale);
        }
        __syncthreads();

        {
            float* sr = &Ss[srow * 68 + (seg << 4)];
            float mt = -1e30f;
#pragma unroll
            for (int jj = 0; jj < 16; ++jj) mt = fmaxf(mt, sr[jj]);
            mt = fmaxf(mt, __shfl_xor_sync(0xffffffffu, mt, 1));
            mt = fmaxf(mt, __shfl_xor_sync(0xffffffffu, mt, 2));
            float m_new = fmaxf(m_i, mt);
            float alpha = __expf(m_i - m_new);
            float ls = 0.f;
#pragma unroll
            for (int jj = 0; jj < 16; ++jj) {
                float p = __expf(sr[jj] - m_new);
                ls += p;
                sr[jj] = f2tff(p);
            }
            ls += __shfl_xor_sync(0xffffffffu, ls, 1);
            ls += __shfl_xor_sync(0xffffffffu, ls, 2);
            l_i = l_i * alpha + ls;
            m_i = m_new;
            if (seg == 0) Al[srow] = alpha;
        }
        __syncthreads();

        float aLo = Al[m0 + g], aHi = Al[m0 + g + 8];
#pragma unroll
        for (int nt = 0; nt < 8; ++nt) {
            oacc[nt][0] *= aLo; oacc[nt][1] *= aLo;
            oacc[nt][2] *= aHi; oacc[nt][3] *= aHi;
        }
#pragma unroll
        for (int kd = 0; kd < 64; kd += 8) {
            uint32_t a[4];
            a[0] = __float_as_uint(Ss[(m0 + g) * 68 + kd + tq]);
            a[1] = __float_as_uint(Ss[(m0 + g + 8) * 68 + kd + tq]);
            a[2] = __float_as_uint(Ss[(m0 + g) * 68 + kd + tq + 4]);
            a[3] = __float_as_uint(Ss[(m0 + g + 8) * 68 + kd + tq + 4]);
#pragma unroll
            for (int nt = 0; nt < 8; ++nt) {
                int dcol = on0 + (nt << 3) + g;
                uint32_t bb[2];
                bb[0] = __float_as_uint(Ks[(kd + tq) * 132 + dcol]);
                bb[1] = __float_as_uint(Ks[(kd + tq + 4) * 132 + dcol]);
                mma8(oacc[nt], a, bb);
            }
        }
    }
    __syncthreads();
    if (seg == 0) Al[srow] = 1.0f / l_i;
    __syncthreads();

    const int iwLo = (qt << 6) + m0 + g;
    const int iwHi = iwLo + 8;
    const int sLo = base + iwLo, sHi = base + iwHi;
    const float triLo = 0.5f + (float)iwLo * (1.0f / 511.0f);
    const float triHi = 0.5f + (float)iwHi * (1.0f / 511.0f);
    float* dLo = L + ((size_t)b * 4096u + sLo) * 1024u + (h << 7);
    float* dHi = dLo + (size_t)8 * 1024u;
    if (parity == 0) {
        const bool snLo = (sLo < 256) || (sLo >= 3840);
        const bool snHi = (sHi < 256) || (sHi >= 3840);
        const float twLo = (snLo ? 1.0f : triLo) * Al[m0 + g];
        const float twHi = (snHi ? 1.0f : triHi) * Al[m0 + g + 8];
#pragma unroll
        for (int nt = 0; nt < 8; ++nt) {
            int dc = on0 + (nt << 3) + (tq << 1);
            *(float2*)(dLo + dc) = make_float2(oacc[nt][0] * twLo, oacc[nt][1] * twLo);
            *(float2*)(dHi + dc) = make_float2(oacc[nt][2] * twHi, oacc[nt][3] * twHi);
        }
    } else {
        const float twLo = triLo * Al[m0 + g];
        const float twHi = triHi * Al[m0 + g + 8];
        const float ivLo = invden(sLo), ivHi = invden(sHi);
#pragma unroll
        for (int nt = 0; nt < 8; ++nt) {
            int dc = on0 + (nt << 3) + (tq << 1);
            float2 o = *(float2*)(dLo + dc);
            o.x = (o.x + oacc[nt][0] * twLo) * ivLo;
            o.y = (o.y + oacc[nt][1] * twLo) * ivLo;
            *(float2*)(dLo + dc) = o;
            float2 p = *(float2*)(dHi + dc);
            p.x = (p.x + oacc[nt][2] * twHi) * ivHi;
            p.y = (p.y + oacc[nt][3] * twHi) * ivHi;
            *(float2*)(dHi + dc) = p;
        }
    }
}

// ============ 4) compressed-global attention (TC) ============
__global__ void __launch_bounds__(256) gattn(
        const float* __restrict__ x, const float* __restrict__ gmem,
        const float* __restrict__ comp, float* __restrict__ G) {
    extern __shared__ float sm[];
    float* KVs = sm;
    float* Qs  = sm + 16896;
    float* Ps  = sm + 21120;
    const int tid = threadIdx.x;
    const int lane = tid & 31, wid = tid >> 5;
    const int g = lane >> 2, tq = lane & 3;
    const int s0 = blockIdx.x << 5, h = blockIdx.y, b = blockIdx.z;

#pragma unroll
    for (int it = 0; it < 16; ++it) {
        int i = tid + (it << 8);
        int r = i >> 5, c4 = (i & 31) << 2;
        float4 v;
        if (r < 64) v = *(const float4*)(comp + (size_t)((b << 6) + r) * 1024u + (h << 7) + c4);
        else        v = *(const float4*)(gmem + (size_t)((h << 6) + (r - 64)) * 128u + c4);
        float* kv = &KVs[r * 132 + c4];
        kv[0] = f2tff(v.x); kv[1] = f2tff(v.y); kv[2] = f2tff(v.z); kv[3] = f2tff(v.w);
    }
#pragma unroll
    for (int it = 0; it < 4; ++it) {
        int i = tid + (it << 8);
        int r = i >> 5, c4 = (i & 31) << 2;
        float4 v = *(const float4*)(x + (size_t)b * 4194304u + (size_t)(s0 + r) * 1024u + (h << 7) + c4);
        float* q = &Qs[r * 132 + c4];
        q[0] = f2tff(v.x); q[1] = f2tff(v.y); q[2] = f2tff(v.z); q[3] = f2tff(v.w);
    }
    __syncthreads();

    const int wm = wid & 1, wn = wid >> 1;
    const int m0 = wm << 4;
    const int tn0 = wn << 5;
    const float scale = 0.08838834764831845f;

    {
        float sacc[4][4];
#pragma unroll
        for (int nt = 0; nt < 4; ++nt)
#pragma unroll
            for (int e = 0; e < 4; ++e) sacc[nt][e] = 0.f;
#pragma unroll
        for (int kd = 0; kd < 128; kd += 8) {
            uint32_t a[4];
            a[0] = __float_as_uint(Qs[(m0 + g) * 132 + kd + tq]);
            a[1] = __float_as_uint(Qs[(m0 + g + 8) * 132 + kd + tq]);
            a[2] = __float_as_uint(Qs[(m0 + g) * 132 + kd + tq + 4]);
            a[3] = __float_as_uint(Qs[(m0 + g + 8) * 132 + kd + tq + 4]);
#pragma unroll
            for (int nt = 0; nt < 4; ++nt) {
                int tcol = tn0 + (nt << 3) + g;
                uint32_t bb[2];
                bb[0] = __float_as_uint(KVs[tcol * 132 + kd + tq]);
                bb[1] = __float_as_uint(KVs[tcol * 132 + kd + tq + 4]);
                mma8(sacc[nt], a, bb);
            }
        }
#pragma unroll
        for (int nt = 0; nt < 4; ++nt) {
            int nc = tn0 + (nt << 3) + (tq << 1);
            *(float2*)&Ps[(m0 + g) * 132 + nc] =
                make_float2(sacc[nt][0] * scale, sacc[nt][1] * scale);
            *(float2*)&Ps[(m0 + g + 8) * 132 + nc] =
                make_float2(sacc[nt][2] * scale, sacc[nt][3] * scale);
        }
    }
    __syncthreads();

    {
        int row = tid >> 3, seg8 = tid & 7;
        float* pr = &Ps[row * 132 + (seg8 << 4)];
        float mt = -1e30f;
        float pv[16];
#pragma unroll
        for (int jj = 0; jj < 16; ++jj) mt = fmaxf(mt, pr[jj]);
        mt = fmaxf(mt, __shfl_xor_sync(0xffffffffu, mt, 1));
        mt = fmaxf(mt, __shfl_xor_sync(0xffffffffu, mt, 2));
        mt = fmaxf(mt, __shfl_xor_sync(0xffffffffu, mt, 4));
        float ssum = 0.f;
#pragma unroll
        for (int jj = 0; jj < 16; ++jj) { pv[jj] = __expf(pr[jj] - mt); ssum += pv[jj]; }
        ssum += __shfl_xor_sync(0xffffffffu, ssum, 1);
        ssum += __shfl_xor_sync(0xffffffffu, ssum, 2);
        ssum += __shfl_xor_sync(0xffffffffu, ssum, 4);
        float invs = 1.0f / ssum;
#pragma unroll
        for (int jj = 0; jj < 16; ++jj) pr[jj] = f2tff(pv[jj] * invs);
    }
    __syncthreads();

    {
        float oacc[4][4];
#pragma unroll
        for (int nt = 0; nt < 4; ++nt)
#pragma unroll
            for (int e = 0; e < 4; ++e) oacc[nt][e] = 0.f;
#pragma unroll
        for (int kd = 0; kd < 128; kd += 8) {
            uint32_t a[4];
            a[0] = __float_as_uint(Ps[(m0 + g) * 132 + kd + tq]);
            a[1] = __float_as_uint(Ps[(m0 + g + 8) * 132 + kd + tq]);
            a[2] = __float_as_uint(Ps[(m0 + g) * 132 + kd + tq + 4]);
            a[3] = __float_as_uint(Ps[(m0 + g + 8) * 132 + kd + tq + 4]);
#pragma unroll
            for (int nt = 0; nt < 4; ++nt) {
                int dcol = tn0 + (nt << 3) + g;
                uint32_t bb[2];
                bb[0] = __float_as_uint(KVs[(kd + tq) * 132 + dcol]);
                bb[1] = __float_as_uint(KVs[(kd + tq + 4) * 132 + dcol]);
                mma8(oacc[nt], a, bb);
            }
        }
        float* gLo = G + ((size_t)b * 4096u + s0 + m0 + g) * 1024u + (h << 7);
        float* gHi = gLo + (size_t)8 * 1024u;
#pragma unroll
        for (int nt = 0; nt < 4; ++nt) {
            int nc = tn0 + (nt << 3) + (tq << 1);
            *(float2*)(gLo + nc) = make_float2(oacc[nt][0], oacc[nt][1]);
            *(float2*)(gHi + nc) = make_float2(oacc[nt][2], oacc[nt][3]);
        }
    }
}

// ============ 5+6) cp.async-pipelined tf32 GEMM (mma.sync) ============
__global__ void __launch_bounds__(256) gemm_tc(
        int mode, const float* __restrict__ A0, const float* __restrict__ A1,
        const float* __restrict__ BCp, const float* __restrict__ W,
        const float* __restrict__ bias, float* __restrict__ C, int K) {
    extern __shared__ float gsm[];
    const int tid = threadIdx.x;
    const int m0 = blockIdx.x << 7, n0 = blockIdx.y << 7;
    const int wid = tid >> 5, lane = tid & 31;
    const int quad = lane >> 2, tq = lane & 3;
    const int wm = wid >> 2, wn = wid & 3;
    const int am = tid >> 1, ak = (tid & 1) << 4;
    const int bk = tid >> 3, bn = (tid & 7) << 4;
    const uint32_t sbase = smem_u32(gsm);

    auto issue = [&](int kt, int slot) {
        uint32_t aoff = sbase + (uint32_t)(slot * 8960 + am * 36 + ak) * 4u;
        const float* asrc = (mode == 1 && kt >= 1024)
            ? (A1 + (size_t)(m0 + am) * 1024u + (kt - 1024) + ak)
            : (A0 + (size_t)(m0 + am) * 1024u + kt + ak);
        CP16(aoff, asrc); CP16(aoff + 16, asrc + 4);
        CP16(aoff + 32, asrc + 8); CP16(aoff + 48, asrc + 12);
        uint32_t boff = sbase + (uint32_t)(slot * 8960 + 4608 + bk * 136 + bn) * 4u;
        const float* bsrc = W + (size_t)(kt + bk) * 1024u + n0 + bn;
        CP16(boff, bsrc); CP16(boff + 16, bsrc + 4);
        CP16(boff + 32, bsrc + 8); CP16(boff + 48, bsrc + 12);
        CPCOMMIT();
    };

    float acc[4][4][4];
#pragma unroll
    for (int i = 0; i < 4; ++i)
#pragma unroll
        for (int j = 0; j < 4; ++j)
#pragma unroll
            for (int e = 0; e < 4; ++e) acc[i][j][e] = 0.f;

    issue(0, 0);
    issue(32, 1);

    for (int kt = 0; kt < K; kt += 32) {
        CPWAIT1();
        __syncthreads();
        int nk = kt + 64;
        if (nk < K) issue(nk, ((kt >> 5) + 2) % 3);
        else        CPCOMMIT();

        const float* Asb = gsm + ((kt >> 5) % 3) * 8960;
        const float* Bsb = Asb + 4608;
#pragma unroll
        for (int ks = 0; ks < 4; ++ks) {
            const int k0 = ks << 3;
            uint32_t af[4][4], bf[4][2];
#pragma unroll
            for (int i = 0; i < 4; ++i) {
                int r = (wm << 6) + (i << 4) + quad;
                af[i][0] = __float_as_uint(Asb[r * 36 + k0 + tq]);
                af[i][1] = __float_as_uint(Asb[(r + 8) * 36 + k0 + tq]);
                af[i][2] = __float_as_uint(Asb[r * 36 + k0 + tq + 4]);
                af[i][3] = __float_as_uint(Asb[(r + 8) * 36 + k0 + tq + 4]);
            }
#pragma unroll
            for (int j = 0; j < 4; ++j) {
                int cidx = (wn << 5) + (j << 3) + quad;
                bf[j][0] = __float_as_uint(Bsb[(k0 + tq) * 136 + cidx]);
                bf[j][1] = __float_as_uint(Bsb[(k0 + tq + 4) * 136 + cidx]);
            }
#pragma unroll
            for (int i = 0; i < 4; ++i)
#pragma unroll
                for (int j = 0; j < 4; ++j) mma8(acc[i][j], af[i], bf[j]);
        }
    }

#pragma unroll
    for (int i = 0; i < 4; ++i)
#pragma unroll
        for (int j = 0; j < 4; ++j) {
            int mr = m0 + (wm << 6) + (i << 4) + quad;
            int nc = n0 + (wn << 5) + (j << 3) + (tq << 1);
#pragma unroll
            for (int hf = 0; hf < 2; ++hf) {
                int m = mr + (hf << 3);
                size_t bix = (size_t)m * 1024u + nc;
#pragma unroll
                for (int e = 0; e < 2; ++e) {
                    float z = acc[i][j][(hf << 1) + e] + bias[nc + e];
                    if (mode == 1) {
                        float gg = 1.0f / (1.0f + __expf(-z));
                        C[bix + e] = gg * A0[bix + e] + (1.0f - gg) * A1[bix + e] + BCp[bix + e];
                    } else {
                        C[bix + e] = z;
                    }
                }
            }
        }
}

// =====================================================================
extern "C" void kernel_launch(void* const* d_in, const int* in_sizes, int n_in,
                              void* d_out, int out_size) {
    const float* x    = (const float*)d_in[0];
    const float* gmem = (const float*)d_in[1];
    const float* cw   = (const float*)d_in[2];
    const float* cb   = (const float*)d_in[3];
    const float* mw   = (const float*)d_in[4];
    const float* mb   = (const float*)d_in[5];
    const float* ow   = (const float*)d_in[6];
    const float* ob   = (const float*)d_in[7];
    float* out = (float*)d_out;

    float *pL, *pG, *pBC, *pM, *pCOMP, *pW1, *pW2, *pXC, *pCP;
    cudaGetSymbolAddress((void**)&pL,    g_L);
    cudaGetSymbolAddress((void**)&pG,    g_G);
    cudaGetSymbolAddress((void**)&pBC,   g_BC);
    cudaGetSymbolAddress((void**)&pM,    g_M);
    cudaGetSymbolAddress((void**)&pCOMP, g_COMP);
    cudaGetSymbolAddress((void**)&pW1,   g_W1);
    cudaGetSymbolAddress((void**)&pW2,   g_W2);
    cudaGetSymbolAddress((void**)&pXC,   g_XC);
    cudaGetSymbolAddress((void**)&pCP,   g_CP);

    static cudaStream_t s1 = nullptr, s2 = nullptr, s3 = nullptr;
    static cudaEvent_t evR = nullptr, ev1 = nullptr, ev2 = nullptr, ev3 = nullptr;
    if (s1 == nullptr) {
        cudaStreamCreateWithFlags(&s1, cudaStreamNonBlocking);
        cudaStreamCreateWithFlags(&s2, cudaStreamNonBlocking);
        cudaStreamCreateWithFlags(&s3, cudaStreamNonBlocking);
        cudaEventCreateWithFlags(&evR, cudaEventDisableTiming);
        cudaEventCreateWithFlags(&ev1, cudaEventDisableTiming);
        cudaEventCreateWithFlags(&ev2, cudaEventDisableTiming);
        cudaEventCreateWithFlags(&ev3, cudaEventDisableTiming);
    }

    const int BC_SMEM = 2 * 16384 * 4;     // 128 KB
    const int WA_SMEM = 21312 * 4;
    const int GA_SMEM = 25344 * 4;
    const int GE_SMEM = 3 * 8960 * 4;      // 107520 B
    const int CV_SMEM = 3 * 9216 * 4;      // 110592 B
    cudaFuncSetAttribute(bc_kernel, cudaFuncAttributeMaxDynamicSharedMemorySize, BC_SMEM);
    cudaFuncSetAttribute(win_attn,  cudaFuncAttributeMaxDynamicSharedMemorySize, WA_SMEM);
    cudaFuncSetAttribute(gattn,     cudaFuncAttributeMaxDynamicSharedMemorySize, GA_SMEM);
    cudaFuncSetAttribute(gemm_tc,   cudaFuncAttributeMaxDynamicSharedMemorySize, GE_SMEM);
    cudaFuncSetAttribute(conv_gemm, cudaFuncAttributeMaxDynamicSharedMemorySize, CV_SMEM);

    cudaEventRecord(evR, 0);
    cudaStreamWaitEvent(s1, evR, 0);
    cudaStreamWaitEvent(s2, evR, 0);
    cudaStreamWaitEvent(s3, evR, 0);

    wround     <<<2048, 256, 0, s1>>>(mw, pW1);
    wround     <<<1024, 256, 0, s1>>>(ow, pW2);
    bc_kernel  <<<dim3(256, 2), 512, BC_SMEM, s1>>>(x, pBC);

    xc_kernel  <<<dim3(256, 2), 256, 0, s2>>>(x, pXC);
    conv_gemm  <<<dim3(8, 4), 256, CV_SMEM, s2>>>(pXC, cw, pCP);
    conv_reduce<<<128, 256, 0, s2>>>(pCP, cb, pCOMP);
    gattn      <<<dim3(128, 8, 2), 256, GA_SMEM, s2>>>(x, gmem, pCOMP, pG);

    win_attn   <<<dim3(8, 8, 16), 256, WA_SMEM, s3>>>(x, pL, 0);
    win_attn   <<<dim3(8, 7, 16), 256, WA_SMEM, s3>>>(x, pL, 1);

    cudaEventRecord(ev1, s1);
    cudaEventRecord(ev2, s2);
    cudaEventRecord(ev3, s3);
    cudaStreamWaitEvent(0, ev1, 0);
    cudaStreamWaitEvent(0, ev2, 0);
    cudaStreamWaitEvent(0, ev3, 0);

    gemm_tc<<<dim3(64, 8), 256, GE_SMEM>>>(1, pL, pG, pBC, pW1, mb, pM, 2048);
    gemm_tc<<<dim3(64, 8), 256, GE_SMEM>>>(0, pM, pM, pBC, pW2, ob, out, 1024);
}